// round 6
// baseline (speedup 1.0000x reference)
#include <cuda_runtime.h>

// Blur_by_Kernel: per-batch 21x21 cross-correlation, reflect pad 10.
// input (16,3,768,768) fp32, kernel (16,21,21) fp32.
// out[b,c,y,x] = sum_{ky,kx} in[b,c, refl(y+ky-10), refl(x+kx-10)] * w[b,ky,kx]
//
// R6: same proven mainloop as R5 (scalar FFMA, 28-float sliding window reused
// by RPT=4 output rows). Structural tweaks: 256-thread CTAs with 128x64 tiles
// (3 CTAs/SM, same 24 warps) -> y-halo redundancy 1.63->1.31, weight loads
// amortized 2x; div-free 2D prologue loop.

namespace {
constexpr int HW   = 768;
constexpr int KS   = 21;
constexpr int PAD  = 10;
constexpr int CPT  = 8;                  // cols per thread
constexpr int RPT  = 4;                  // rows per thread
constexpr int TXN  = 16, TYN = 16;
constexpr int TILE_X = CPT * TXN;        // 128
constexpr int TILE_Y = RPT * TYN;        // 64
constexpr int SM_W = TILE_X + 2 * PAD;   // 148 floats (592B rows, 16B aligned)
constexpr int SM_H = TILE_Y + 2 * PAD;   // 84 rows
constexpr int WSTRIDE = 24;              // padded weight row (96B, 16B aligned)
constexpr int NT   = TXN * TYN;          // 256
}

// one weight-row pass: acc[j] += sum_kx v[kx+j] * w[kx]
__device__ __forceinline__ void do_pass(float (&acc)[CPT],
                                        const float* __restrict__ wr,
                                        const float (&v)[28])
{
    #pragma unroll
    for (int g = 0; g < 5; ++g) {
        const float4 w = *(const float4*)(wr + 4 * g);   // broadcast LDS.128
        #pragma unroll
        for (int j = 0; j < CPT; ++j) acc[j] = fmaf(v[4*g + 0 + j], w.x, acc[j]);
        #pragma unroll
        for (int j = 0; j < CPT; ++j) acc[j] = fmaf(v[4*g + 1 + j], w.y, acc[j]);
        #pragma unroll
        for (int j = 0; j < CPT; ++j) acc[j] = fmaf(v[4*g + 2 + j], w.z, acc[j]);
        #pragma unroll
        for (int j = 0; j < CPT; ++j) acc[j] = fmaf(v[4*g + 3 + j], w.w, acc[j]);
    }
    const float wl = wr[20];
    #pragma unroll
    for (int j = 0; j < CPT; ++j) acc[j] = fmaf(v[20 + j], wl, acc[j]);
}

__global__ __launch_bounds__(NT, 3)
void blur21_kernel(const float* __restrict__ in,
                   const float* __restrict__ wts,
                   float* __restrict__ out)
{
    __shared__ float tile[SM_H][SM_W];
    __shared__ float sw[KS * WSTRIDE];

    const int bc  = blockIdx.z;           // b*3 + c
    const int b   = bc / 3;
    const int bx  = blockIdx.x * TILE_X;
    const int by  = blockIdx.y * TILE_Y;
    const int tid = threadIdx.x;
    const int tx  = tid & 15;             // 0..15
    const int ty  = tid >> 4;             // 0..15

    const float* __restrict__ img = in + (size_t)bc * (HW * HW);

    // weights for this batch, rows padded to WSTRIDE
    for (int i = tid; i < KS * WSTRIDE; i += NT) {
        const int r = i / WSTRIDE, c = i - r * WSTRIDE;
        sw[i] = (c < KS) ? wts[b * (KS * KS) + r * KS + c] : 0.f;
    }

    // input tile with reflect indexing, div-free 2D loop over (r, c)
    #pragma unroll 1
    for (int r = ty; r < SM_H; r += TYN) {
        int gy = by + r - PAD;
        gy = (gy < 0) ? -gy : ((gy >= HW) ? (2 * HW - 2 - gy) : gy);
        const float* __restrict__ row = img + (size_t)gy * HW;
        #pragma unroll 1
        for (int c = tx; c < SM_W; c += TXN) {
            int gx = bx + c - PAD;
            gx = (gx < 0) ? -gx : ((gx >= HW) ? (2 * HW - 2 - gx) : gx);
            tile[r][c] = row[gx];
        }
    }
    __syncthreads();

    const int ox = tx * CPT;              // 32B-aligned smem col base
    const int oy = ty * RPT;

    float acc0[CPT], acc1[CPT], acc2[CPT], acc3[CPT];
    #pragma unroll
    for (int j = 0; j < CPT; ++j) {
        acc0[j] = 0.f; acc1[j] = 0.f; acc2[j] = 0.f; acc3[j] = 0.f;
    }

    float v[28];
    #define LOADW(s)                                                     \
        do {                                                             \
            const float4* __restrict__ p =                               \
                (const float4*)&tile[oy + (s)][ox];                      \
            _Pragma("unroll")                                            \
            for (int i = 0; i < 7; ++i) {                                \
                const float4 q = p[i];                                   \
                v[4*i+0] = q.x; v[4*i+1] = q.y;                          \
                v[4*i+2] = q.z; v[4*i+3] = q.w;                          \
            }                                                            \
        } while (0)

    // window row s feeds output row r (0..3) with weight row (s - r)
    LOADW(0);
    do_pass(acc0, &sw[0 * WSTRIDE], v);

    LOADW(1);
    do_pass(acc0, &sw[1 * WSTRIDE], v);
    do_pass(acc1, &sw[0 * WSTRIDE], v);

    LOADW(2);
    do_pass(acc0, &sw[2 * WSTRIDE], v);
    do_pass(acc1, &sw[1 * WSTRIDE], v);
    do_pass(acc2, &sw[0 * WSTRIDE], v);

    #pragma unroll 1
    for (int s = 3; s <= 20; ++s) {
        LOADW(s);
        const float* __restrict__ w0 = &sw[s * WSTRIDE];
        do_pass(acc0, w0, v);
        do_pass(acc1, w0 - WSTRIDE, v);
        do_pass(acc2, w0 - 2 * WSTRIDE, v);
        do_pass(acc3, w0 - 3 * WSTRIDE, v);
    }

    LOADW(21);
    do_pass(acc1, &sw[20 * WSTRIDE], v);
    do_pass(acc2, &sw[19 * WSTRIDE], v);
    do_pass(acc3, &sw[18 * WSTRIDE], v);

    LOADW(22);
    do_pass(acc2, &sw[20 * WSTRIDE], v);
    do_pass(acc3, &sw[19 * WSTRIDE], v);

    LOADW(23);
    do_pass(acc3, &sw[20 * WSTRIDE], v);

    #undef LOADW

    float* __restrict__ o = out + (size_t)bc * (HW * HW)
                                + (size_t)(by + oy) * HW + (bx + ox);
    *(float4*)(o)              = make_float4(acc0[0], acc0[1], acc0[2], acc0[3]);
    *(float4*)(o + 4)          = make_float4(acc0[4], acc0[5], acc0[6], acc0[7]);
    *(float4*)(o + HW)         = make_float4(acc1[0], acc1[1], acc1[2], acc1[3]);
    *(float4*)(o + HW + 4)     = make_float4(acc1[4], acc1[5], acc1[6], acc1[7]);
    *(float4*)(o + 2 * HW)     = make_float4(acc2[0], acc2[1], acc2[2], acc2[3]);
    *(float4*)(o + 2 * HW + 4) = make_float4(acc2[4], acc2[5], acc2[6], acc2[7]);
    *(float4*)(o + 3 * HW)     = make_float4(acc3[0], acc3[1], acc3[2], acc3[3]);
    *(float4*)(o + 3 * HW + 4) = make_float4(acc3[4], acc3[5], acc3[6], acc3[7]);
}

extern "C" void kernel_launch(void* const* d_in, const int* in_sizes, int n_in,
                              void* d_out, int out_size)
{
    const float* img = (const float*)d_in[0];
    const float* wts = (const float*)d_in[1];
    if (n_in >= 2 && in_sizes[0] == 16 * KS * KS) {   // 7056 -> kernel tensor
        img = (const float*)d_in[1];
        wts = (const float*)d_in[0];
    }

    dim3 grid(HW / TILE_X, HW / TILE_Y, 16 * 3);
    blur21_kernel<<<grid, NT>>>(img, wts, (float*)d_out);
}

// round 7
// speedup vs baseline: 1.0157x; 1.0157x over previous
#include <cuda_runtime.h>

// Blur_by_Kernel: per-batch 21x21 cross-correlation, reflect pad 10.
// input (16,3,768,768) fp32, kernel (16,21,21) fp32.
// out[b,c,y,x] = sum_{ky,kx} in[b,c, refl(y+ky-10), refl(x+kx-10)] * w[b,ky,kx]
//
// R7 = R5 winner geometry (128-thread CTAs, 128x32 tile, 6 CTAs/SM, 24 warps;
// scalar FFMA sliding-window mainloop) + R6's proven div-free 2D prologue.
// R6 taught: at equal warps/SM, small CTAs >> large CTAs (barrier skew +
// independent-CTA overlap). Tensor cores rejected for good: per-(b,c) this is
// a matrix-VECTOR product (N=1), min-N=8 wastes >=8x of the MMA.

namespace {
constexpr int HW   = 768;
constexpr int KS   = 21;
constexpr int PAD  = 10;
constexpr int CPT  = 8;                  // cols per thread
constexpr int RPT  = 4;                  // rows per thread
constexpr int TXN  = 16, TYN = 8;
constexpr int TILE_X = CPT * TXN;        // 128
constexpr int TILE_Y = RPT * TYN;        // 32
constexpr int SM_W = TILE_X + 2 * PAD;   // 148 floats (592B rows, 16B aligned)
constexpr int SM_H = TILE_Y + 2 * PAD;   // 52 rows
constexpr int WSTRIDE = 24;              // padded weight row (96B, 16B aligned)
constexpr int NT   = TXN * TYN;          // 128
}

// one weight-row pass: acc[j] += sum_kx v[kx+j] * w[kx]
__device__ __forceinline__ void do_pass(float (&acc)[CPT],
                                        const float* __restrict__ wr,
                                        const float (&v)[28])
{
    #pragma unroll
    for (int g = 0; g < 5; ++g) {
        const float4 w = *(const float4*)(wr + 4 * g);   // broadcast LDS.128
        #pragma unroll
        for (int j = 0; j < CPT; ++j) acc[j] = fmaf(v[4*g + 0 + j], w.x, acc[j]);
        #pragma unroll
        for (int j = 0; j < CPT; ++j) acc[j] = fmaf(v[4*g + 1 + j], w.y, acc[j]);
        #pragma unroll
        for (int j = 0; j < CPT; ++j) acc[j] = fmaf(v[4*g + 2 + j], w.z, acc[j]);
        #pragma unroll
        for (int j = 0; j < CPT; ++j) acc[j] = fmaf(v[4*g + 3 + j], w.w, acc[j]);
    }
    const float wl = wr[20];
    #pragma unroll
    for (int j = 0; j < CPT; ++j) acc[j] = fmaf(v[20 + j], wl, acc[j]);
}

__global__ __launch_bounds__(NT, 6)
void blur21_kernel(const float* __restrict__ in,
                   const float* __restrict__ wts,
                   float* __restrict__ out)
{
    __shared__ float tile[SM_H][SM_W];
    __shared__ float sw[KS * WSTRIDE];

    const int bc  = blockIdx.z;           // b*3 + c
    const int b   = bc / 3;
    const int bx  = blockIdx.x * TILE_X;
    const int by  = blockIdx.y * TILE_Y;
    const int tid = threadIdx.x;
    const int tx  = tid & 15;             // 0..15
    const int ty  = tid >> 4;             // 0..7

    const float* __restrict__ img = in + (size_t)bc * (HW * HW);

    // weights for this batch, rows padded to WSTRIDE (504 floats, 128 threads)
    for (int i = tid; i < KS * WSTRIDE; i += NT) {
        const int r = i / WSTRIDE, c = i - r * WSTRIDE;
        sw[i] = (c < KS) ? wts[b * (KS * KS) + r * KS + c] : 0.f;
    }

    // input tile with reflect indexing, div-free 2D loop over (r, c)
    #pragma unroll 1
    for (int r = ty; r < SM_H; r += TYN) {
        int gy = by + r - PAD;
        gy = (gy < 0) ? -gy : ((gy >= HW) ? (2 * HW - 2 - gy) : gy);
        const float* __restrict__ row = img + (size_t)gy * HW;
        #pragma unroll 1
        for (int c = tx; c < SM_W; c += TXN) {
            int gx = bx + c - PAD;
            gx = (gx < 0) ? -gx : ((gx >= HW) ? (2 * HW - 2 - gx) : gx);
            tile[r][c] = row[gx];
        }
    }
    __syncthreads();

    const int ox = tx * CPT;              // 32B-aligned smem col base
    const int oy = ty * RPT;

    float acc0[CPT], acc1[CPT], acc2[CPT], acc3[CPT];
    #pragma unroll
    for (int j = 0; j < CPT; ++j) {
        acc0[j] = 0.f; acc1[j] = 0.f; acc2[j] = 0.f; acc3[j] = 0.f;
    }

    float v[28];
    #define LOADW(s)                                                     \
        do {                                                             \
            const float4* __restrict__ p =                               \
                (const float4*)&tile[oy + (s)][ox];                      \
            _Pragma("unroll")                                            \
            for (int i = 0; i < 7; ++i) {                                \
                const float4 q = p[i];                                   \
                v[4*i+0] = q.x; v[4*i+1] = q.y;                          \
                v[4*i+2] = q.z; v[4*i+3] = q.w;                          \
            }                                                            \
        } while (0)

    // window row s feeds output row r (0..3) with weight row (s - r)
    LOADW(0);
    do_pass(acc0, &sw[0 * WSTRIDE], v);

    LOADW(1);
    do_pass(acc0, &sw[1 * WSTRIDE], v);
    do_pass(acc1, &sw[0 * WSTRIDE], v);

    LOADW(2);
    do_pass(acc0, &sw[2 * WSTRIDE], v);
    do_pass(acc1, &sw[1 * WSTRIDE], v);
    do_pass(acc2, &sw[0 * WSTRIDE], v);

    #pragma unroll 1
    for (int s = 3; s <= 20; ++s) {
        LOADW(s);
        const float* __restrict__ w0 = &sw[s * WSTRIDE];
        do_pass(acc0, w0, v);
        do_pass(acc1, w0 - WSTRIDE, v);
        do_pass(acc2, w0 - 2 * WSTRIDE, v);
        do_pass(acc3, w0 - 3 * WSTRIDE, v);
    }

    LOADW(21);
    do_pass(acc1, &sw[20 * WSTRIDE], v);
    do_pass(acc2, &sw[19 * WSTRIDE], v);
    do_pass(acc3, &sw[18 * WSTRIDE], v);

    LOADW(22);
    do_pass(acc2, &sw[20 * WSTRIDE], v);
    do_pass(acc3, &sw[19 * WSTRIDE], v);

    LOADW(23);
    do_pass(acc3, &sw[20 * WSTRIDE], v);

    #undef LOADW

    float* __restrict__ o = out + (size_t)bc * (HW * HW)
                                + (size_t)(by + oy) * HW + (bx + ox);
    *(float4*)(o)              = make_float4(acc0[0], acc0[1], acc0[2], acc0[3]);
    *(float4*)(o + 4)          = make_float4(acc0[4], acc0[5], acc0[6], acc0[7]);
    *(float4*)(o + HW)         = make_float4(acc1[0], acc1[1], acc1[2], acc1[3]);
    *(float4*)(o + HW + 4)     = make_float4(acc1[4], acc1[5], acc1[6], acc1[7]);
    *(float4*)(o + 2 * HW)     = make_float4(acc2[0], acc2[1], acc2[2], acc2[3]);
    *(float4*)(o + 2 * HW + 4) = make_float4(acc2[4], acc2[5], acc2[6], acc2[7]);
    *(float4*)(o + 3 * HW)     = make_float4(acc3[0], acc3[1], acc3[2], acc3[3]);
    *(float4*)(o + 3 * HW + 4) = make_float4(acc3[4], acc3[5], acc3[6], acc3[7]);
}

extern "C" void kernel_launch(void* const* d_in, const int* in_sizes, int n_in,
                              void* d_out, int out_size)
{
    const float* img = (const float*)d_in[0];
    const float* wts = (const float*)d_in[1];
    if (n_in >= 2 && in_sizes[0] == 16 * KS * KS) {   // 7056 -> kernel tensor
        img = (const float*)d_in[1];
        wts = (const float*)d_in[0];
    }

    dim3 grid(HW / TILE_X, HW / TILE_Y, 16 * 3);
    blur21_kernel<<<grid, NT>>>(img, wts, (float*)d_out);
}

// round 8
// speedup vs baseline: 1.1506x; 1.1328x over previous
#include <cuda_runtime.h>

// Blur_by_Kernel: per-batch 21x21 cross-correlation, reflect pad 10.
// input (16,3,768,768) fp32, kernel (16,21,21) fp32.
// out[b,c,y,x] = sum_{ky,kx} in[b,c, refl(y+ky-10), refl(x+kx-10)] * w[b,ky,kx]
//
// R8 = R5 (430.6us winner: 128-thread CTAs, 128x32 tile, 6 CTAs/SM, scalar
// FFMA sliding-window mainloop) with ONLY the prologue changed:
//  - flat loop, NO unroll pragma (R6/R7 lesson: "#pragma unroll 1" serialized
//    the tile-fill LDGs to MLP=1 and cost ~60us; ptxas unrolling batches them)
//  - div-free incremental (r,c) bookkeeping; smem store addr is linear i.

namespace {
constexpr int HW   = 768;
constexpr int KS   = 21;
constexpr int PAD  = 10;
constexpr int CPT  = 8;                  // cols per thread
constexpr int RPT  = 4;                  // rows per thread
constexpr int TXN  = 16, TYN = 8;
constexpr int TILE_X = CPT * TXN;        // 128
constexpr int TILE_Y = RPT * TYN;        // 32
constexpr int SM_W = TILE_X + 2 * PAD;   // 148 floats (592B rows, 16B aligned)
constexpr int SM_H = TILE_Y + 2 * PAD;   // 52 rows
constexpr int WSTRIDE = 24;              // padded weight row (96B, 16B aligned)
constexpr int NT   = TXN * TYN;          // 128  (NT <= SM_W, prologue relies on it)
}

// one weight-row pass: acc[j] += sum_kx v[kx+j] * w[kx]
__device__ __forceinline__ void do_pass(float (&acc)[CPT],
                                        const float* __restrict__ wr,
                                        const float (&v)[28])
{
    #pragma unroll
    for (int g = 0; g < 5; ++g) {
        const float4 w = *(const float4*)(wr + 4 * g);   // broadcast LDS.128
        #pragma unroll
        for (int j = 0; j < CPT; ++j) acc[j] = fmaf(v[4*g + 0 + j], w.x, acc[j]);
        #pragma unroll
        for (int j = 0; j < CPT; ++j) acc[j] = fmaf(v[4*g + 1 + j], w.y, acc[j]);
        #pragma unroll
        for (int j = 0; j < CPT; ++j) acc[j] = fmaf(v[4*g + 2 + j], w.z, acc[j]);
        #pragma unroll
        for (int j = 0; j < CPT; ++j) acc[j] = fmaf(v[4*g + 3 + j], w.w, acc[j]);
    }
    const float wl = wr[20];
    #pragma unroll
    for (int j = 0; j < CPT; ++j) acc[j] = fmaf(v[20 + j], wl, acc[j]);
}

__global__ __launch_bounds__(NT, 6)
void blur21_kernel(const float* __restrict__ in,
                   const float* __restrict__ wts,
                   float* __restrict__ out)
{
    __shared__ float tile[SM_H][SM_W];
    __shared__ float sw[KS * WSTRIDE];

    const int bc  = blockIdx.z;           // b*3 + c
    const int b   = bc / 3;
    const int bx  = blockIdx.x * TILE_X;
    const int by  = blockIdx.y * TILE_Y;
    const int tid = threadIdx.x;

    const float* __restrict__ img = in + (size_t)bc * (HW * HW);

    // weights for this batch, rows padded to WSTRIDE (504 floats)
    for (int i = tid; i < KS * WSTRIDE; i += NT) {
        const int r = i / WSTRIDE, c = i - r * WSTRIDE;
        sw[i] = (c < KS) ? wts[b * (KS * KS) + r * KS + c] : 0.f;
    }

    // input tile with reflect indexing: flat loop (ptxas unrolls -> batched
    // LDGs, MLP preserved), div-free incremental (r,c) carry.
    {
        float* __restrict__ tl = &tile[0][0];
        int r = 0, c = tid;               // NT <= SM_W so first row covers tid
        for (int i = tid; i < SM_H * SM_W; i += NT) {
            int gy = by + r - PAD;
            gy = (gy < 0) ? -gy : ((gy >= HW) ? (2 * HW - 2 - gy) : gy);
            int gx = bx + c - PAD;
            gx = (gx < 0) ? -gx : ((gx >= HW) ? (2 * HW - 2 - gx) : gx);
            tl[i] = img[gy * HW + gx];
            c += NT;
            if (c >= SM_W) { c -= SM_W; ++r; }
        }
    }
    __syncthreads();

    const int tx = tid & 15;              // 0..15
    const int ty = tid >> 4;              // 0..7
    const int ox = tx * CPT;              // 32B-aligned smem col base
    const int oy = ty * RPT;

    float acc0[CPT], acc1[CPT], acc2[CPT], acc3[CPT];
    #pragma unroll
    for (int j = 0; j < CPT; ++j) {
        acc0[j] = 0.f; acc1[j] = 0.f; acc2[j] = 0.f; acc3[j] = 0.f;
    }

    float v[28];
    #define LOADW(s)                                                     \
        do {                                                             \
            const float4* __restrict__ p =                               \
                (const float4*)&tile[oy + (s)][ox];                      \
            _Pragma("unroll")                                            \
            for (int i = 0; i < 7; ++i) {                                \
                const float4 q = p[i];                                   \
                v[4*i+0] = q.x; v[4*i+1] = q.y;                          \
                v[4*i+2] = q.z; v[4*i+3] = q.w;                          \
            }                                                            \
        } while (0)

    // window row s feeds output row r (0..3) with weight row (s - r)
    LOADW(0);
    do_pass(acc0, &sw[0 * WSTRIDE], v);

    LOADW(1);
    do_pass(acc0, &sw[1 * WSTRIDE], v);
    do_pass(acc1, &sw[0 * WSTRIDE], v);

    LOADW(2);
    do_pass(acc0, &sw[2 * WSTRIDE], v);
    do_pass(acc1, &sw[1 * WSTRIDE], v);
    do_pass(acc2, &sw[0 * WSTRIDE], v);

    #pragma unroll 1
    for (int s = 3; s <= 20; ++s) {
        LOADW(s);
        const float* __restrict__ w0 = &sw[s * WSTRIDE];
        do_pass(acc0, w0, v);
        do_pass(acc1, w0 - WSTRIDE, v);
        do_pass(acc2, w0 - 2 * WSTRIDE, v);
        do_pass(acc3, w0 - 3 * WSTRIDE, v);
    }

    LOADW(21);
    do_pass(acc1, &sw[20 * WSTRIDE], v);
    do_pass(acc2, &sw[19 * WSTRIDE], v);
    do_pass(acc3, &sw[18 * WSTRIDE], v);

    LOADW(22);
    do_pass(acc2, &sw[20 * WSTRIDE], v);
    do_pass(acc3, &sw[19 * WSTRIDE], v);

    LOADW(23);
    do_pass(acc3, &sw[20 * WSTRIDE], v);

    #undef LOADW

    float* __restrict__ o = out + (size_t)bc * (HW * HW)
                                + (size_t)(by + oy) * HW + (bx + ox);
    *(float4*)(o)              = make_float4(acc0[0], acc0[1], acc0[2], acc0[3]);
    *(float4*)(o + 4)          = make_float4(acc0[4], acc0[5], acc0[6], acc0[7]);
    *(float4*)(o + HW)         = make_float4(acc1[0], acc1[1], acc1[2], acc1[3]);
    *(float4*)(o + HW + 4)     = make_float4(acc1[4], acc1[5], acc1[6], acc1[7]);
    *(float4*)(o + 2 * HW)     = make_float4(acc2[0], acc2[1], acc2[2], acc2[3]);
    *(float4*)(o + 2 * HW + 4) = make_float4(acc2[4], acc2[5], acc2[6], acc2[7]);
    *(float4*)(o + 3 * HW)     = make_float4(acc3[0], acc3[1], acc3[2], acc3[3]);
    *(float4*)(o + 3 * HW + 4) = make_float4(acc3[4], acc3[5], acc3[6], acc3[7]);
}

extern "C" void kernel_launch(void* const* d_in, const int* in_sizes, int n_in,
                              void* d_out, int out_size)
{
    const float* img = (const float*)d_in[0];
    const float* wts = (const float*)d_in[1];
    if (n_in >= 2 && in_sizes[0] == 16 * KS * KS) {   // 7056 -> kernel tensor
        img = (const float*)d_in[1];
        wts = (const float*)d_in[0];
    }

    dim3 grid(HW / TILE_X, HW / TILE_Y, 16 * 3);
    blur21_kernel<<<grid, NT>>>(img, wts, (float*)d_out);
}

// round 9
// speedup vs baseline: 1.1657x; 1.0131x over previous
#include <cuda_runtime.h>

// Blur_by_Kernel: per-batch 21x21 cross-correlation, reflect pad 10.
// input (16,3,768,768) fp32, kernel (16,21,21) fp32.
// out[b,c,y,x] = sum_{ky,kx} in[b,c, refl(y+ky-10), refl(x+kx-10)] * w[b,ky,kx]
//
// R9 = R8 mainloop (430us-class: 128-thread CTAs, 128x32 tile, 6 CTAs/SM,
// scalar-FFMA sliding window, flat high-MLP loads) + vectorized prologue:
//  - x-interior blocks (4/6): rows loaded as aligned LDG.128 from bx-12
//    (38 float4/row, warp-strided rows, fully unrolled -> batched LDGs),
//    scattered with predicated STS.32. ~16 LDG.128/thread vs 60 LDG.32.
//  - x-edge blocks (bx=0,640): R8 scalar reflect path unchanged.

namespace {
constexpr int HW   = 768;
constexpr int KS   = 21;
constexpr int PAD  = 10;
constexpr int CPT  = 8;                  // cols per thread
constexpr int RPT  = 4;                  // rows per thread
constexpr int TXN  = 16, TYN = 8;
constexpr int TILE_X = CPT * TXN;        // 128
constexpr int TILE_Y = RPT * TYN;        // 32
constexpr int SM_W = TILE_X + 2 * PAD;   // 148 floats (592B rows, 16B aligned)
constexpr int SM_H = TILE_Y + 2 * PAD;   // 52 rows
constexpr int WSTRIDE = 24;              // padded weight row (96B, 16B aligned)
constexpr int NT   = TXN * TYN;          // 128
constexpr int FPR  = 38;                 // float4 units per row in fast path
}

// one weight-row pass: acc[j] += sum_kx v[kx+j] * w[kx]
__device__ __forceinline__ void do_pass(float (&acc)[CPT],
                                        const float* __restrict__ wr,
                                        const float (&v)[28])
{
    #pragma unroll
    for (int g = 0; g < 5; ++g) {
        const float4 w = *(const float4*)(wr + 4 * g);   // broadcast LDS.128
        #pragma unroll
        for (int j = 0; j < CPT; ++j) acc[j] = fmaf(v[4*g + 0 + j], w.x, acc[j]);
        #pragma unroll
        for (int j = 0; j < CPT; ++j) acc[j] = fmaf(v[4*g + 1 + j], w.y, acc[j]);
        #pragma unroll
        for (int j = 0; j < CPT; ++j) acc[j] = fmaf(v[4*g + 2 + j], w.z, acc[j]);
        #pragma unroll
        for (int j = 0; j < CPT; ++j) acc[j] = fmaf(v[4*g + 3 + j], w.w, acc[j]);
    }
    const float wl = wr[20];
    #pragma unroll
    for (int j = 0; j < CPT; ++j) acc[j] = fmaf(v[20 + j], wl, acc[j]);
}

__global__ __launch_bounds__(NT, 6)
void blur21_kernel(const float* __restrict__ in,
                   const float* __restrict__ wts,
                   float* __restrict__ out)
{
    __shared__ float tile[SM_H][SM_W];
    __shared__ float sw[KS * WSTRIDE];

    const int bc  = blockIdx.z;           // b*3 + c
    const int b   = bc / 3;
    const int bx  = blockIdx.x * TILE_X;
    const int by  = blockIdx.y * TILE_Y;
    const int tid = threadIdx.x;

    const float* __restrict__ img = in + (size_t)bc * (HW * HW);

    // weights for this batch, rows padded to WSTRIDE (504 floats)
    for (int i = tid; i < KS * WSTRIDE; i += NT) {
        const int r = i / WSTRIDE, c = i - r * WSTRIDE;
        sw[i] = (c < KS) ? wts[b * (KS * KS) + r * KS + c] : 0.f;
    }

    if (bx >= TILE_X && bx + TILE_X + PAD <= HW) {
        // ---- fast prologue: no x-reflection possible for this block ----
        // gmem row span [bx-12, bx+140) is 16B-aligned; FPR=38 float4/row.
        // warp w handles rows w, w+4, ..., w+48 (13 rows, fully unrolled).
        const int w   = tid >> 5;
        const int ln  = tid & 31;
        const float* __restrict__ base = img + bx - 12;
        #pragma unroll
        for (int k = 0; k < 13; ++k) {
            const int r = w + 4 * k;
            int gy = by + r - PAD;
            gy = (gy < 0) ? -gy : ((gy >= HW) ? (2 * HW - 2 - gy) : gy);
            const float4* __restrict__ gp = (const float4*)(base + (size_t)gy * HW);

            {   // unit u = ln (0..31)
                const float4 q = gp[ln];
                const int c0 = 4 * ln - 2;                 // -2..122
                if (c0 >= 0)     tile[r][c0]     = q.x;
                if (c0 + 1 >= 0) tile[r][c0 + 1] = q.y;
                tile[r][c0 + 2] = q.z;
                tile[r][c0 + 3] = q.w;
            }
            if (ln < FPR - 32) {                           // unit u = 32+ln (32..37)
                const float4 q = gp[32 + ln];
                const int c0 = 4 * (32 + ln) - 2;          // 126..146
                tile[r][c0]     = q.x;
                tile[r][c0 + 1] = q.y;
                if (c0 + 2 < SM_W) tile[r][c0 + 2] = q.z;
                if (c0 + 3 < SM_W) tile[r][c0 + 3] = q.w;
            }
        }
    } else {
        // ---- edge prologue (bx==0 or bx==640): scalar reflect path ----
        float* __restrict__ tl = &tile[0][0];
        int r = 0, c = tid;               // NT <= SM_W so first row covers tid
        for (int i = tid; i < SM_H * SM_W; i += NT) {
            int gy = by + r - PAD;
            gy = (gy < 0) ? -gy : ((gy >= HW) ? (2 * HW - 2 - gy) : gy);
            int gx = bx + c - PAD;
            gx = (gx < 0) ? -gx : ((gx >= HW) ? (2 * HW - 2 - gx) : gx);
            tl[i] = img[gy * HW + gx];
            c += NT;
            if (c >= SM_W) { c -= SM_W; ++r; }
        }
    }
    __syncthreads();

    const int tx = tid & 15;              // 0..15
    const int ty = tid >> 4;              // 0..7
    const int ox = tx * CPT;              // 32B-aligned smem col base
    const int oy = ty * RPT;

    float acc0[CPT], acc1[CPT], acc2[CPT], acc3[CPT];
    #pragma unroll
    for (int j = 0; j < CPT; ++j) {
        acc0[j] = 0.f; acc1[j] = 0.f; acc2[j] = 0.f; acc3[j] = 0.f;
    }

    float v[28];
    #define LOADW(s)                                                     \
        do {                                                             \
            const float4* __restrict__ p =                               \
                (const float4*)&tile[oy + (s)][ox];                      \
            _Pragma("unroll")                                            \
            for (int i = 0; i < 7; ++i) {                                \
                const float4 q = p[i];                                   \
                v[4*i+0] = q.x; v[4*i+1] = q.y;                          \
                v[4*i+2] = q.z; v[4*i+3] = q.w;                          \
            }                                                            \
        } while (0)

    // window row s feeds output row r (0..3) with weight row (s - r)
    LOADW(0);
    do_pass(acc0, &sw[0 * WSTRIDE], v);

    LOADW(1);
    do_pass(acc0, &sw[1 * WSTRIDE], v);
    do_pass(acc1, &sw[0 * WSTRIDE], v);

    LOADW(2);
    do_pass(acc0, &sw[2 * WSTRIDE], v);
    do_pass(acc1, &sw[1 * WSTRIDE], v);
    do_pass(acc2, &sw[0 * WSTRIDE], v);

    #pragma unroll 1
    for (int s = 3; s <= 20; ++s) {
        LOADW(s);
        const float* __restrict__ w0 = &sw[s * WSTRIDE];
        do_pass(acc0, w0, v);
        do_pass(acc1, w0 - WSTRIDE, v);
        do_pass(acc2, w0 - 2 * WSTRIDE, v);
        do_pass(acc3, w0 - 3 * WSTRIDE, v);
    }

    LOADW(21);
    do_pass(acc1, &sw[20 * WSTRIDE], v);
    do_pass(acc2, &sw[19 * WSTRIDE], v);
    do_pass(acc3, &sw[18 * WSTRIDE], v);

    LOADW(22);
    do_pass(acc2, &sw[20 * WSTRIDE], v);
    do_pass(acc3, &sw[19 * WSTRIDE], v);

    LOADW(23);
    do_pass(acc3, &sw[20 * WSTRIDE], v);

    #undef LOADW

    float* __restrict__ o = out + (size_t)bc * (HW * HW)
                                + (size_t)(by + oy) * HW + (bx + ox);
    *(float4*)(o)              = make_float4(acc0[0], acc0[1], acc0[2], acc0[3]);
    *(float4*)(o + 4)          = make_float4(acc0[4], acc0[5], acc0[6], acc0[7]);
    *(float4*)(o + HW)         = make_float4(acc1[0], acc1[1], acc1[2], acc1[3]);
    *(float4*)(o + HW + 4)     = make_float4(acc1[4], acc1[5], acc1[6], acc1[7]);
    *(float4*)(o + 2 * HW)     = make_float4(acc2[0], acc2[1], acc2[2], acc2[3]);
    *(float4*)(o + 2 * HW + 4) = make_float4(acc2[4], acc2[5], acc2[6], acc2[7]);
    *(float4*)(o + 3 * HW)     = make_float4(acc3[0], acc3[1], acc3[2], acc3[3]);
    *(float4*)(o + 3 * HW + 4) = make_float4(acc3[4], acc3[5], acc3[6], acc3[7]);
}

extern "C" void kernel_launch(void* const* d_in, const int* in_sizes, int n_in,
                              void* d_out, int out_size)
{
    const float* img = (const float*)d_in[0];
    const float* wts = (const float*)d_in[1];
    if (n_in >= 2 && in_sizes[0] == 16 * KS * KS) {   // 7056 -> kernel tensor
        img = (const float*)d_in[1];
        wts = (const float*)d_in[0];
    }

    dim3 grid(HW / TILE_X, HW / TILE_Y, 16 * 3);
    blur21_kernel<<<grid, NT>>>(img, wts, (float*)d_out);
}